// round 12
// baseline (speedup 1.0000x reference)
#include <cuda_runtime.h>
#include <cuda_fp16.h>
#include <cstdint>

// ---------------------------------------------------------------------------
// Problem constants
// ---------------------------------------------------------------------------
static constexpr int Bz   = 8192;   // batch
static constexpr int Hd   = 1024;   // hidden
static constexpr int Ktot = 2048;   // IN + H
static constexpr int Ntot = 4096;   // 4H
static constexpr float EPSV = 1e-5f;

// GEMM tiling: 128x128x64, 3 stages, 4 warps of 64x64, 2 CTAs/SM  (R6 champion)
static constexpr int BM = 128;
static constexpr int BN = 128;
static constexpr int BK = 64;
static constexpr int STAGES = 3;
static constexpr int NTHREADS = 128;

static constexpr int ROW_HALVES = BK + 8;              // 72 halves = 144B padded row
static constexpr int ROW_BYTES  = ROW_HALVES * 2;      // 144
static constexpr int TILE_BYTES = BM * ROW_BYTES;      // 18432 (A); B same
static constexpr int STAGE_BYTES = 2 * TILE_BYTES;     // 36864
static constexpr int SMEM_BYTES  = STAGES * STAGE_BYTES; // 110592 (x2 CTA = 216KB)

static constexpr int NB_M = Bz / BM;    // 64
static constexpr int NB_N = Ntot / BN;  // 32
static constexpr int GM   = 8;          // raster group

// ---------------------------------------------------------------------------
// Static device scratch (allocation-free rule)
// ---------------------------------------------------------------------------
__device__ __half g_A16[(size_t)Bz * Ktot];    // [8192, 2048] fp16  (32 MB)
__device__ __half g_W16[(size_t)Ntot * Ktot];  // [4096, 2048] fp16  (16 MB)
__device__ float  g_G[(size_t)Bz * Ntot];      // [8192, 4096] fp32  (128 MB)

// ---------------------------------------------------------------------------
// PTX helpers (plain sm_80/90 features only)
// ---------------------------------------------------------------------------
__device__ __forceinline__ uint32_t smem_u32(const void* p) {
    uint32_t a;
    asm("{ .reg .u64 t; cvta.to.shared.u64 t, %1; cvt.u32.u64 %0, t; }"
        : "=r"(a) : "l"(p));
    return a;
}

#define CP_ASYNC16(saddr, gptr) \
    asm volatile("cp.async.cg.shared.global [%0], [%1], 16;" \
                 :: "r"(saddr), "l"(gptr) : "memory")
#define CP_COMMIT() asm volatile("cp.async.commit_group;" ::: "memory")
#define CP_WAIT1()  asm volatile("cp.async.wait_group 1;" ::: "memory")

#define LDMATRIX_X4(r0, r1, r2, r3, addr) \
    asm volatile("ldmatrix.sync.aligned.m8n8.x4.shared.b16 {%0,%1,%2,%3}, [%4];" \
                 : "=r"(r0), "=r"(r1), "=r"(r2), "=r"(r3) : "r"(addr))

#define MMA16816(c0, c1, c2, c3, a0, a1, a2, a3, b0, b1) \
    asm volatile("mma.sync.aligned.m16n8k16.row.col.f32.f16.f16.f32 " \
                 "{%0,%1,%2,%3}, {%4,%5,%6,%7}, {%8,%9}, {%0,%1,%2,%3};" \
                 : "+f"(c0), "+f"(c1), "+f"(c2), "+f"(c3) \
                 : "r"(a0), "r"(a1), "r"(a2), "r"(a3), "r"(b0), "r"(b1))

// ---------------------------------------------------------------------------
// Kernel 1: pack fp32 inputs/weights -> fp16 A=[x|h], W=[w_i|w_h]  (champion)
// ---------------------------------------------------------------------------
__global__ void __launch_bounds__(256)
convert_kernel(const float4* __restrict__ x, const float4* __restrict__ h,
               const float4* __restrict__ wi, const float4* __restrict__ wh) {
    const int NA = Bz * 1024 / 4;
    const int NW = Ntot * 1024 / 4;
    const int total = 2 * NA + 2 * NW;
    int stride = gridDim.x * blockDim.x;
    for (int i = blockIdx.x * blockDim.x + threadIdx.x; i < total; i += stride) {
        float4 v;
        size_t dofs;
        __half* dst;
        if (i < NA) {
            v = x[i];  int m = i >> 8, k4 = i & 255;
            dst = g_A16; dofs = (size_t)m * Ktot + k4 * 4;
        } else if (i < 2 * NA) {
            int j = i - NA; v = h[j]; int m = j >> 8, k4 = j & 255;
            dst = g_A16; dofs = (size_t)m * Ktot + 1024 + k4 * 4;
        } else if (i < 2 * NA + NW) {
            int j = i - 2 * NA; v = wi[j]; int n = j >> 8, k4 = j & 255;
            dst = g_W16; dofs = (size_t)n * Ktot + k4 * 4;
        } else {
            int j = i - 2 * NA - NW; v = wh[j]; int n = j >> 8, k4 = j & 255;
            dst = g_W16; dofs = (size_t)n * Ktot + 1024 + k4 * 4;
        }
        __half2 h0 = __floats2half2_rn(v.x, v.y);
        __half2 h1 = __floats2half2_rn(v.z, v.w);
        uint2 u;
        u.x = *reinterpret_cast<uint32_t*>(&h0);
        u.y = *reinterpret_cast<uint32_t*>(&h1);
        *reinterpret_cast<uint2*>(dst + dofs) = u;
    }
}

// ---------------------------------------------------------------------------
// Kernel 2: pipelined mma.sync fp16 GEMM (EXACT R6 champion)
// ---------------------------------------------------------------------------
__global__ void __launch_bounds__(NTHREADS, 2)
gemm_kernel(const __half* __restrict__ A, const __half* __restrict__ W,
            float* __restrict__ G) {
    extern __shared__ __align__(128) char smem[];
    const uint32_t sb = smem_u32(smem);

    const int tid = threadIdx.x;
    const int wid = tid >> 5, lane = tid & 31;

    int pid = blockIdx.x;
    const int per_group = GM * NB_N;
    int bm = (pid / per_group) * GM + (pid % per_group) % GM;
    int bn = (pid % per_group) / GM;
    const int m0 = bm * BM;
    const int n0 = bn * BN;

    const int kstart = (bn >= 16 && bn < 24) ? (1024 / BK) : 0;
    const int nkt    = (Ktot / BK) - kstart;

    int rT[8], cT[8];
    const __half* gA[8]; const __half* gB[8];
    uint32_t sA[8], sB[8];
    #pragma unroll
    for (int j = 0; j < 8; j++) {
        int c = tid + j * NTHREADS;
        rT[j] = c >> 3; cT[j] = c & 7;
        gA[j] = A + (size_t)(m0 + rT[j]) * Ktot + cT[j] * 8;
        gB[j] = W + (size_t)(n0 + rT[j]) * Ktot + cT[j] * 8;
        sA[j] = sb + rT[j] * ROW_BYTES + cT[j] * 16;
        sB[j] = sb + TILE_BYTES + rT[j] * ROW_BYTES + cT[j] * 16;
    }
    const size_t kinc = (size_t)kstart * BK;

    const int wm0 = (wid & 1) * 64;
    const int wn0 = (wid >> 1) * 64;

    const int a_row = wm0 + (lane & 15);
    const int a_kc  = lane >> 4;
    const int b_row = wn0 + ((lane >> 4) << 3) + (lane & 7);
    const int b_kc  = (lane >> 3) & 1;

    float acc[4][8][4];
    #pragma unroll
    for (int i = 0; i < 4; i++)
        #pragma unroll
        for (int j = 0; j < 8; j++)
            #pragma unroll
            for (int c = 0; c < 4; c++) acc[i][j][c] = 0.f;

    #pragma unroll
    for (int s = 0; s < STAGES - 1; s++) {
        size_t ko = kinc + (size_t)s * BK;
        uint32_t so = s * STAGE_BYTES;
        #pragma unroll
        for (int j = 0; j < 8; j++) CP_ASYNC16(sA[j] + so, gA[j] + ko);
        #pragma unroll
        for (int j = 0; j < 8; j++) CP_ASYNC16(sB[j] + so, gB[j] + ko);
        CP_COMMIT();
    }

    int stage = 0, nstage = STAGES - 1;
    for (int kt = 0; kt < nkt; kt++) {
        CP_WAIT1();
        __syncthreads();

        int nx = kt + STAGES - 1;
        if (nx < nkt) {
            size_t ko = kinc + (size_t)nx * BK;
            uint32_t so = nstage * STAGE_BYTES;
            #pragma unroll
            for (int j = 0; j < 8; j++) CP_ASYNC16(sA[j] + so, gA[j] + ko);
            #pragma unroll
            for (int j = 0; j < 8; j++) CP_ASYNC16(sB[j] + so, gB[j] + ko);
        }
        CP_COMMIT();
        if (++nstage == STAGES) nstage = 0;

        const uint32_t stA = sb + stage * STAGE_BYTES;
        const uint32_t stB = stA + TILE_BYTES;
        if (++stage == STAGES) stage = 0;

        #pragma unroll
        for (int ks = 0; ks < 4; ks++) {
            uint32_t a[4][4];
            #pragma unroll
            for (int mt = 0; mt < 4; mt++) {
                uint32_t addr = stA + (a_row + mt * 16) * ROW_BYTES
                              + (ks * 2 + a_kc) * 16;
                LDMATRIX_X4(a[mt][0], a[mt][1], a[mt][2], a[mt][3], addr);
            }
            uint32_t b[8][2];
            #pragma unroll
            for (int p = 0; p < 4; p++) {
                uint32_t addr = stB + (b_row + p * 16) * ROW_BYTES
                              + (ks * 2 + b_kc) * 16;
                uint32_t r0, r1, r2, r3;
                LDMATRIX_X4(r0, r1, r2, r3, addr);
                b[p * 2 + 0][0] = r0; b[p * 2 + 0][1] = r1;
                b[p * 2 + 1][0] = r2; b[p * 2 + 1][1] = r3;
            }
            #pragma unroll
            for (int mt = 0; mt < 4; mt++)
                #pragma unroll
                for (int ng = 0; ng < 8; ng++)
                    MMA16816(acc[mt][ng][0], acc[mt][ng][1],
                             acc[mt][ng][2], acc[mt][ng][3],
                             a[mt][0], a[mt][1], a[mt][2], a[mt][3],
                             b[ng][0], b[ng][1]);
        }
    }

    const int er = lane >> 2;
    const int ec = (lane & 3) * 2;
    #pragma unroll
    for (int mt = 0; mt < 4; mt++) {
        #pragma unroll
        for (int ng = 0; ng < 8; ng++) {
            int row = m0 + wm0 + mt * 16 + er;
            int col = n0 + wn0 + ng * 8 + ec;
            float* p0 = G + (size_t)row * Ntot + col;
            float* p1 = G + (size_t)(row + 8) * Ntot + col;
            *reinterpret_cast<float2*>(p0) = make_float2(acc[mt][ng][0], acc[mt][ng][1]);
            *reinterpret_cast<float2*>(p1) = make_float2(acc[mt][ng][2], acc[mt][ng][3]);
        }
    }
}

// ---------------------------------------------------------------------------
// Kernel 3: per-row LayerNorm-LSTM gating
//   float4 loads (thread owns 4 consecutive cols), 1 barrier per reduction
//   via alternating smem buffers + per-thread cross-warp sum.
// ---------------------------------------------------------------------------
__device__ __forceinline__ float sigmoidf_(float v) { return 1.f / (1.f + expf(-v)); }

// One barrier per call. sh is one of two alternating buffers.
__device__ __forceinline__ void block_reduce(float* v, int cnt, float sh[8][6]) {
    int lane = threadIdx.x & 31, w = threadIdx.x >> 5;
    #pragma unroll
    for (int c = 0; c < 6; c++) {
        if (c >= cnt) break;
        float xv = v[c];
        #pragma unroll
        for (int o = 16; o; o >>= 1) xv += __shfl_xor_sync(0xffffffffu, xv, o);
        if (lane == 0) sh[w][c] = xv;
    }
    __syncthreads();
    #pragma unroll
    for (int c = 0; c < 6; c++) {
        if (c >= cnt) break;
        v[c] = ((sh[0][c] + sh[1][c]) + (sh[2][c] + sh[3][c]))
             + ((sh[4][c] + sh[5][c]) + (sh[6][c] + sh[7][c]));
    }
}

__global__ void __launch_bounds__(256)
ln_lstm_kernel(const float* __restrict__ G, const float* __restrict__ c_prev,
               const float* __restrict__ li_g, const float* __restrict__ li_b,
               const float* __restrict__ lh_g, const float* __restrict__ lh_b,
               const float* __restrict__ lg_g, const float* __restrict__ lg_b,
               const float* __restrict__ lo_g, const float* __restrict__ lo_b,
               const float* __restrict__ lc_g, const float* __restrict__ lc_b,
               float* __restrict__ out) {
    __shared__ float sh[2][8][6];
    int b = blockIdx.x, tid = threadIdx.x;
    const float4* g4  = reinterpret_cast<const float4*>(G + (size_t)b * Ntot);
    const float4* cp4 = reinterpret_cast<const float4*>(c_prev + (size_t)b * Hd);
    const float inv = 1.f / 1024.f;

    // thread owns columns 4*tid .. 4*tid+3 of each gate
    float a0[4], a1[4], a2[4], a3[4], cp[4];
    *reinterpret_cast<float4*>(a0) = g4[tid];          // gate i
    *reinterpret_cast<float4*>(a1) = g4[256 + tid];    // gate f
    *reinterpret_cast<float4*>(a2) = g4[512 + tid];    // h_g preactivation
    *reinterpret_cast<float4*>(a3) = g4[768 + tid];    // gate o
    *reinterpret_cast<float4*>(cp) = cp4[tid];

    float s[6] = {0.f, 0.f, 0.f, 0.f, 0.f, 0.f};
    #pragma unroll
    for (int j = 0; j < 4; j++) {
        s[0] += a0[j]; s[1] += a0[j] * a0[j];
        s[2] += a1[j]; s[3] += a1[j] * a1[j];
        s[4] += a3[j]; s[5] += a3[j] * a3[j];
    }
    block_reduce(s, 6, sh[0]);
    float mu0 = s[0] * inv, r0 = rsqrtf(s[1] * inv - mu0 * mu0 + EPSV);
    float mu1 = s[2] * inv, r1 = rsqrtf(s[3] * inv - mu1 * mu1 + EPSV);
    float mu3 = s[4] * inv, r3 = rsqrtf(s[5] * inv - mu3 * mu3 + EPSV);

    // params: float4 loads (thread's 4 consecutive cols)
    float pig[4], pib[4], phg[4], phb[4], pgg[4], pgb[4], pog[4], pob[4], pcg[4], pcb[4];
    *reinterpret_cast<float4*>(pig) = reinterpret_cast<const float4*>(li_g)[tid];
    *reinterpret_cast<float4*>(pib) = reinterpret_cast<const float4*>(li_b)[tid];
    *reinterpret_cast<float4*>(phg) = reinterpret_cast<const float4*>(lh_g)[tid];
    *reinterpret_cast<float4*>(phb) = reinterpret_cast<const float4*>(lh_b)[tid];
    *reinterpret_cast<float4*>(pgg) = reinterpret_cast<const float4*>(lg_g)[tid];
    *reinterpret_cast<float4*>(pgb) = reinterpret_cast<const float4*>(lg_b)[tid];
    *reinterpret_cast<float4*>(pog) = reinterpret_cast<const float4*>(lo_g)[tid];
    *reinterpret_cast<float4*>(pob) = reinterpret_cast<const float4*>(lo_b)[tid];
    *reinterpret_cast<float4*>(pcg) = reinterpret_cast<const float4*>(lc_g)[tid];
    *reinterpret_cast<float4*>(pcb) = reinterpret_cast<const float4*>(lc_b)[tid];

    float ig[4], fg[4], og[4], tt[4];
    float t[6] = {0.f, 0.f, 0.f, 0.f, 0.f, 0.f};
    #pragma unroll
    for (int j = 0; j < 4; j++) {
        ig[j] = sigmoidf_((a0[j] - mu0) * r0 * pig[j] + pib[j]);
        fg[j] = sigmoidf_((a1[j] - mu1) * r1 * phg[j] + phb[j]);
        og[j] = sigmoidf_((a3[j] - mu3) * r3 * pog[j] + pob[j]);
        tt[j] = ig[j] + a2[j];       // source bug: sigmoided i_g + h_g
        t[0] += tt[j]; t[1] += tt[j] * tt[j];
    }
    block_reduce(t, 2, sh[1]);
    float mut = t[0] * inv, rt = rsqrtf(t[1] * inv - mut * mut + EPSV);

    float cl[4];
    float u[6] = {0.f, 0.f, 0.f, 0.f, 0.f, 0.f};
    #pragma unroll
    for (int j = 0; j < 4; j++) {
        float gg = tanhf((tt[j] - mut) * rt * pgg[j] + pgb[j]);
        cl[j] = fg[j] * cp[j] + ig[j] * gg;
        u[0] += cl[j]; u[1] += cl[j] * cl[j];
    }
    block_reduce(u, 2, sh[0]);
    float muc = u[0] * inv, rc = rsqrtf(u[1] * inv - muc * muc + EPSV);

    float hn[4], cn[4];
    #pragma unroll
    for (int j = 0; j < 4; j++) {
        cn[j] = (cl[j] - muc) * rc * pcg[j] + pcb[j];
        hn[j] = og[j] * tanhf(cn[j]);
    }
    float4* outh = reinterpret_cast<float4*>(out + (size_t)b * Hd);
    float4* outc = reinterpret_cast<float4*>(out + (size_t)Bz * Hd + (size_t)b * Hd);
    outh[tid] = *reinterpret_cast<float4*>(hn);
    outc[tid] = *reinterpret_cast<float4*>(cn);
}

// ---------------------------------------------------------------------------
// Host
// ---------------------------------------------------------------------------
extern "C" void kernel_launch(void* const* d_in, const int* in_sizes, int n_in,
                              void* d_out, int out_size) {
    const float* x  = (const float*)d_in[0];
    const float* h  = (const float*)d_in[1];
    const float* c  = (const float*)d_in[2];
    const float* wi = (const float*)d_in[3];
    const float* wh = (const float*)d_in[4];
    float* out = (float*)d_out;

    void *pA = nullptr, *pW = nullptr, *pG = nullptr;
    cudaGetSymbolAddress(&pA, g_A16);
    cudaGetSymbolAddress(&pW, g_W16);
    cudaGetSymbolAddress(&pG, g_G);

    cudaFuncSetAttribute(gemm_kernel, cudaFuncAttributeMaxDynamicSharedMemorySize,
                         SMEM_BYTES);

    convert_kernel<<<1184, 256>>>((const float4*)x, (const float4*)h,
                                  (const float4*)wi, (const float4*)wh);

    gemm_kernel<<<NB_M * NB_N, NTHREADS, SMEM_BYTES>>>((const __half*)pA,
                                                       (const __half*)pW,
                                                       (float*)pG);

    ln_lstm_kernel<<<Bz, 256>>>((const float*)pG, c,
                                (const float*)d_in[5],  (const float*)d_in[6],
                                (const float*)d_in[7],  (const float*)d_in[8],
                                (const float*)d_in[9],  (const float*)d_in[10],
                                (const float*)d_in[11], (const float*)d_in[12],
                                (const float*)d_in[13], (const float*)d_in[14],
                                out);
    (void)in_sizes; (void)n_in; (void)out_size;
}

// round 13
// speedup vs baseline: 1.0286x; 1.0286x over previous
#include <cuda_runtime.h>
#include <cuda_fp16.h>
#include <cstdint>

// ---------------------------------------------------------------------------
// Problem constants
// ---------------------------------------------------------------------------
static constexpr int Bz   = 8192;   // batch
static constexpr int Hd   = 1024;   // hidden
static constexpr int Ktot = 2048;   // IN + H
static constexpr int Ntot = 4096;   // 4H
static constexpr float EPSV = 1e-5f;

// GEMM tiling: 128x128x64, 3 stages, 4 warps of 64x64, 2 CTAs/SM  (R6 champion)
static constexpr int BM = 128;
static constexpr int BN = 128;
static constexpr int BK = 64;
static constexpr int STAGES = 3;
static constexpr int NTHREADS = 128;

static constexpr int ROW_HALVES = BK + 8;              // 72 halves = 144B padded row
static constexpr int ROW_BYTES  = ROW_HALVES * 2;      // 144
static constexpr int TILE_BYTES = BM * ROW_BYTES;      // 18432 (A); B same
static constexpr int STAGE_BYTES = 2 * TILE_BYTES;     // 36864
static constexpr int SMEM_BYTES  = STAGES * STAGE_BYTES; // 110592 (x2 CTA = 216KB)

static constexpr int NB_M = Bz / BM;    // 64
static constexpr int NB_N = Ntot / BN;  // 32
static constexpr int GM   = 8;          // raster group

// ---------------------------------------------------------------------------
// Static device scratch (allocation-free rule)
// ---------------------------------------------------------------------------
__device__ __half g_A16[(size_t)Bz * Ktot];    // [8192, 2048] fp16  (32 MB)
__device__ __half g_W16[(size_t)Ntot * Ktot];  // [4096, 2048] fp16  (16 MB)
__device__ float  g_G[(size_t)Bz * Ntot];      // [8192, 4096] fp32  (128 MB)

// ---------------------------------------------------------------------------
// PTX helpers (plain sm_80/90 features only)
// ---------------------------------------------------------------------------
__device__ __forceinline__ uint32_t smem_u32(const void* p) {
    uint32_t a;
    asm("{ .reg .u64 t; cvta.to.shared.u64 t, %1; cvt.u32.u64 %0, t; }"
        : "=r"(a) : "l"(p));
    return a;
}

#define CP_ASYNC16(saddr, gptr) \
    asm volatile("cp.async.cg.shared.global [%0], [%1], 16;" \
                 :: "r"(saddr), "l"(gptr) : "memory")
#define CP_COMMIT() asm volatile("cp.async.commit_group;" ::: "memory")
#define CP_WAIT1()  asm volatile("cp.async.wait_group 1;" ::: "memory")

#define LDMATRIX_X4(r0, r1, r2, r3, addr) \
    asm volatile("ldmatrix.sync.aligned.m8n8.x4.shared.b16 {%0,%1,%2,%3}, [%4];" \
                 : "=r"(r0), "=r"(r1), "=r"(r2), "=r"(r3) : "r"(addr))

#define MMA16816(c0, c1, c2, c3, a0, a1, a2, a3, b0, b1) \
    asm volatile("mma.sync.aligned.m16n8k16.row.col.f32.f16.f16.f32 " \
                 "{%0,%1,%2,%3}, {%4,%5,%6,%7}, {%8,%9}, {%0,%1,%2,%3};" \
                 : "+f"(c0), "+f"(c1), "+f"(c2), "+f"(c3) \
                 : "r"(a0), "r"(a1), "r"(a2), "r"(a3), "r"(b0), "r"(b1))

// ---------------------------------------------------------------------------
// Kernel 1: pack fp32 inputs/weights -> fp16 A=[x|h], W=[w_i|w_h]
//   32B reads (2x float4) -> 16B STG.128 writes; each thread-iter does
//   8 consecutive k-elements, so dst layout is unchanged.
// ---------------------------------------------------------------------------
__global__ void __launch_bounds__(256)
convert_kernel(const float4* __restrict__ x, const float4* __restrict__ h,
               const float4* __restrict__ wi, const float4* __restrict__ wh) {
    // work items of 8 floats (two float4): per A half 8192*128, per W half 4096*128
    const int NA = Bz * 128;     // 1,048,576 items per A half
    const int NW = Ntot * 128;   //   524,288 items per W half
    const int total = 2 * NA + 2 * NW;
    int stride = gridDim.x * blockDim.x;
    for (int i = blockIdx.x * blockDim.x + threadIdx.x; i < total; i += stride) {
        const float4* src;
        __half* dst;
        size_t dofs;
        int j;
        if (i < NA) {
            j = i; src = x;
            int m = j >> 7, k8 = j & 127;
            dst = g_A16; dofs = (size_t)m * Ktot + k8 * 8;
        } else if (i < 2 * NA) {
            j = i - NA; src = h;
            int m = j >> 7, k8 = j & 127;
            dst = g_A16; dofs = (size_t)m * Ktot + 1024 + k8 * 8;
        } else if (i < 2 * NA + NW) {
            j = i - 2 * NA; src = wi;
            int n = j >> 7, k8 = j & 127;
            dst = g_W16; dofs = (size_t)n * Ktot + k8 * 8;
        } else {
            j = i - 2 * NA - NW; src = wh;
            int n = j >> 7, k8 = j & 127;
            dst = g_W16; dofs = (size_t)n * Ktot + 1024 + k8 * 8;
        }
        float4 v0 = src[2 * j];
        float4 v1 = src[2 * j + 1];
        __half2 h0 = __floats2half2_rn(v0.x, v0.y);
        __half2 h1 = __floats2half2_rn(v0.z, v0.w);
        __half2 h2 = __floats2half2_rn(v1.x, v1.y);
        __half2 h3 = __floats2half2_rn(v1.z, v1.w);
        uint4 u;
        u.x = *reinterpret_cast<uint32_t*>(&h0);
        u.y = *reinterpret_cast<uint32_t*>(&h1);
        u.z = *reinterpret_cast<uint32_t*>(&h2);
        u.w = *reinterpret_cast<uint32_t*>(&h3);
        *reinterpret_cast<uint4*>(dst + dofs) = u;
    }
}

// ---------------------------------------------------------------------------
// Kernel 2: pipelined mma.sync fp16 GEMM  G[8192,4096] = A16 @ W16^T
//   EXACT R6 champion: 128x128x64, 3-stage cp.async, 4 warps 64x64, 2 CTAs/SM
//   n-tiles in [2048,3072): accumulate only k >= 1024 (dead-chunk bug)
// ---------------------------------------------------------------------------
__global__ void __launch_bounds__(NTHREADS, 2)
gemm_kernel(const __half* __restrict__ A, const __half* __restrict__ W,
            float* __restrict__ G) {
    extern __shared__ __align__(128) char smem[];
    const uint32_t sb = smem_u32(smem);

    const int tid = threadIdx.x;
    const int wid = tid >> 5, lane = tid & 31;

    int pid = blockIdx.x;
    const int per_group = GM * NB_N;
    int bm = (pid / per_group) * GM + (pid % per_group) % GM;
    int bn = (pid % per_group) / GM;
    const int m0 = bm * BM;
    const int n0 = bn * BN;

    const int kstart = (bn >= 16 && bn < 24) ? (1024 / BK) : 0;
    const int nkt    = (Ktot / BK) - kstart;

    int rT[8], cT[8];
    const __half* gA[8]; const __half* gB[8];
    uint32_t sA[8], sB[8];
    #pragma unroll
    for (int j = 0; j < 8; j++) {
        int c = tid + j * NTHREADS;
        rT[j] = c >> 3; cT[j] = c & 7;
        gA[j] = A + (size_t)(m0 + rT[j]) * Ktot + cT[j] * 8;
        gB[j] = W + (size_t)(n0 + rT[j]) * Ktot + cT[j] * 8;
        sA[j] = sb + rT[j] * ROW_BYTES + cT[j] * 16;
        sB[j] = sb + TILE_BYTES + rT[j] * ROW_BYTES + cT[j] * 16;
    }
    const size_t kinc = (size_t)kstart * BK;

    const int wm0 = (wid & 1) * 64;
    const int wn0 = (wid >> 1) * 64;

    const int a_row = wm0 + (lane & 15);
    const int a_kc  = lane >> 4;
    const int b_row = wn0 + ((lane >> 4) << 3) + (lane & 7);
    const int b_kc  = (lane >> 3) & 1;

    float acc[4][8][4];
    #pragma unroll
    for (int i = 0; i < 4; i++)
        #pragma unroll
        for (int j = 0; j < 8; j++)
            #pragma unroll
            for (int c = 0; c < 4; c++) acc[i][j][c] = 0.f;

    #pragma unroll
    for (int s = 0; s < STAGES - 1; s++) {
        size_t ko = kinc + (size_t)s * BK;
        uint32_t so = s * STAGE_BYTES;
        #pragma unroll
        for (int j = 0; j < 8; j++) CP_ASYNC16(sA[j] + so, gA[j] + ko);
        #pragma unroll
        for (int j = 0; j < 8; j++) CP_ASYNC16(sB[j] + so, gB[j] + ko);
        CP_COMMIT();
    }

    int stage = 0, nstage = STAGES - 1;
    for (int kt = 0; kt < nkt; kt++) {
        CP_WAIT1();
        __syncthreads();

        int nx = kt + STAGES - 1;
        if (nx < nkt) {
            size_t ko = kinc + (size_t)nx * BK;
            uint32_t so = nstage * STAGE_BYTES;
            #pragma unroll
            for (int j = 0; j < 8; j++) CP_ASYNC16(sA[j] + so, gA[j] + ko);
            #pragma unroll
            for (int j = 0; j < 8; j++) CP_ASYNC16(sB[j] + so, gB[j] + ko);
        }
        CP_COMMIT();
        if (++nstage == STAGES) nstage = 0;

        const uint32_t stA = sb + stage * STAGE_BYTES;
        const uint32_t stB = stA + TILE_BYTES;
        if (++stage == STAGES) stage = 0;

        #pragma unroll
        for (int ks = 0; ks < 4; ks++) {
            uint32_t a[4][4];
            #pragma unroll
            for (int mt = 0; mt < 4; mt++) {
                uint32_t addr = stA + (a_row + mt * 16) * ROW_BYTES
                              + (ks * 2 + a_kc) * 16;
                LDMATRIX_X4(a[mt][0], a[mt][1], a[mt][2], a[mt][3], addr);
            }
            uint32_t b[8][2];
            #pragma unroll
            for (int p = 0; p < 4; p++) {
                uint32_t addr = stB + (b_row + p * 16) * ROW_BYTES
                              + (ks * 2 + b_kc) * 16;
                uint32_t r0, r1, r2, r3;
                LDMATRIX_X4(r0, r1, r2, r3, addr);
                b[p * 2 + 0][0] = r0; b[p * 2 + 0][1] = r1;
                b[p * 2 + 1][0] = r2; b[p * 2 + 1][1] = r3;
            }
            #pragma unroll
            for (int mt = 0; mt < 4; mt++)
                #pragma unroll
                for (int ng = 0; ng < 8; ng++)
                    MMA16816(acc[mt][ng][0], acc[mt][ng][1],
                             acc[mt][ng][2], acc[mt][ng][3],
                             a[mt][0], a[mt][1], a[mt][2], a[mt][3],
                             b[ng][0], b[ng][1]);
        }
    }

    const int er = lane >> 2;
    const int ec = (lane & 3) * 2;
    #pragma unroll
    for (int mt = 0; mt < 4; mt++) {
        #pragma unroll
        for (int ng = 0; ng < 8; ng++) {
            int row = m0 + wm0 + mt * 16 + er;
            int col = n0 + wn0 + ng * 8 + ec;
            float* p0 = G + (size_t)row * Ntot + col;
            float* p1 = G + (size_t)(row + 8) * Ntot + col;
            *reinterpret_cast<float2*>(p0) = make_float2(acc[mt][ng][0], acc[mt][ng][1]);
            *reinterpret_cast<float2*>(p1) = make_float2(acc[mt][ng][2], acc[mt][ng][3]);
        }
    }
}

// ---------------------------------------------------------------------------
// Kernel 3: per-row LayerNorm-LSTM gating (EXACT R6 champion form)
// ---------------------------------------------------------------------------
__device__ __forceinline__ float sigmoidf_(float v) { return 1.f / (1.f + expf(-v)); }

__device__ __forceinline__ void block_reduce(float* v, int cnt, float sh[][6], float* bc) {
    int tid = threadIdx.x, lane = tid & 31, w = tid >> 5;
    #pragma unroll
    for (int c = 0; c < 6; c++) {
        if (c >= cnt) break;
        float xv = v[c];
        #pragma unroll
        for (int o = 16; o; o >>= 1) xv += __shfl_xor_sync(0xffffffffu, xv, o);
        if (lane == 0) sh[w][c] = xv;
    }
    __syncthreads();
    if (tid < cnt) {
        float a = 0.f;
        #pragma unroll
        for (int i = 0; i < 8; i++) a += sh[i][tid];
        bc[tid] = a;
    }
    __syncthreads();
    for (int c = 0; c < cnt; c++) v[c] = bc[c];
}

__global__ void __launch_bounds__(256)
ln_lstm_kernel(const float* __restrict__ G, const float* __restrict__ c_prev,
               const float* __restrict__ li_g, const float* __restrict__ li_b,
               const float* __restrict__ lh_g, const float* __restrict__ lh_b,
               const float* __restrict__ lg_g, const float* __restrict__ lg_b,
               const float* __restrict__ lo_g, const float* __restrict__ lo_b,
               const float* __restrict__ lc_g, const float* __restrict__ lc_b,
               float* __restrict__ out) {
    __shared__ float sh[8][6];
    __shared__ float bc[6];
    int b = blockIdx.x, tid = threadIdx.x;
    const float* g = G + (size_t)b * Ntot;
    const float inv = 1.f / 1024.f;

    float a0[4], a1[4], a2[4], a3[4], cp[4];
    float s[6] = {0.f, 0.f, 0.f, 0.f, 0.f, 0.f};
    #pragma unroll
    for (int j = 0; j < 4; j++) {
        int n = tid + j * 256;
        a0[j] = g[n];
        a1[j] = g[1024 + n];
        a2[j] = g[2048 + n];     // = h_g preactivation (w_h-only column block)
        a3[j] = g[3072 + n];
        cp[j] = c_prev[(size_t)b * Hd + n];
        s[0] += a0[j]; s[1] += a0[j] * a0[j];
        s[2] += a1[j]; s[3] += a1[j] * a1[j];
        s[4] += a3[j]; s[5] += a3[j] * a3[j];
    }
    block_reduce(s, 6, sh, bc);
    float mu0 = s[0] * inv, r0 = rsqrtf(s[1] * inv - mu0 * mu0 + EPSV);
    float mu1 = s[2] * inv, r1 = rsqrtf(s[3] * inv - mu1 * mu1 + EPSV);
    float mu3 = s[4] * inv, r3 = rsqrtf(s[5] * inv - mu3 * mu3 + EPSV);

    float ig[4], fg[4], og[4], tt[4];
    float t[6] = {0.f, 0.f, 0.f, 0.f, 0.f, 0.f};
    #pragma unroll
    for (int j = 0; j < 4; j++) {
        int n = tid + j * 256;
        ig[j] = sigmoidf_((a0[j] - mu0) * r0 * li_g[n] + li_b[n]);
        fg[j] = sigmoidf_((a1[j] - mu1) * r1 * lh_g[n] + lh_b[n]);
        og[j] = sigmoidf_((a3[j] - mu3) * r3 * lo_g[n] + lo_b[n]);
        tt[j] = ig[j] + a2[j];       // source bug: sigmoided i_g + h_g
        t[0] += tt[j]; t[1] += tt[j] * tt[j];
    }
    block_reduce(t, 2, sh, bc);
    float mut = t[0] * inv, rt = rsqrtf(t[1] * inv - mut * mut + EPSV);

    float cl[4];
    float u[6] = {0.f, 0.f, 0.f, 0.f, 0.f, 0.f};
    #pragma unroll
    for (int j = 0; j < 4; j++) {
        int n = tid + j * 256;
        float gg = tanhf((tt[j] - mut) * rt * lg_g[n] + lg_b[n]);
        cl[j] = fg[j] * cp[j] + ig[j] * gg;
        u[0] += cl[j]; u[1] += cl[j] * cl[j];
    }
    block_reduce(u, 2, sh, bc);
    float muc = u[0] * inv, rc = rsqrtf(u[1] * inv - muc * muc + EPSV);

    #pragma unroll
    for (int j = 0; j < 4; j++) {
        int n = tid + j * 256;
        float cn = (cl[j] - muc) * rc * lc_g[n] + lc_b[n];
        out[(size_t)Bz * Hd + (size_t)b * Hd + n] = cn;             // c_new
        out[(size_t)b * Hd + n] = og[j] * tanhf(cn);                // h_new
    }
}

// ---------------------------------------------------------------------------
// Host
// ---------------------------------------------------------------------------
extern "C" void kernel_launch(void* const* d_in, const int* in_sizes, int n_in,
                              void* d_out, int out_size) {
    const float* x  = (const float*)d_in[0];
    const float* h  = (const float*)d_in[1];
    const float* c  = (const float*)d_in[2];
    const float* wi = (const float*)d_in[3];
    const float* wh = (const float*)d_in[4];
    float* out = (float*)d_out;

    void *pA = nullptr, *pW = nullptr, *pG = nullptr;
    cudaGetSymbolAddress(&pA, g_A16);
    cudaGetSymbolAddress(&pW, g_W16);
    cudaGetSymbolAddress(&pG, g_G);

    cudaFuncSetAttribute(gemm_kernel, cudaFuncAttributeMaxDynamicSharedMemorySize,
                         SMEM_BYTES);

    convert_kernel<<<1184, 256>>>((const float4*)x, (const float4*)h,
                                  (const float4*)wi, (const float4*)wh);

    gemm_kernel<<<NB_M * NB_N, NTHREADS, SMEM_BYTES>>>((const __half*)pA,
                                                       (const __half*)pW,
                                                       (float*)pG);

    ln_lstm_kernel<<<Bz, 256>>>((const float*)pG, c,
                                (const float*)d_in[5],  (const float*)d_in[6],
                                (const float*)d_in[7],  (const float*)d_in[8],
                                (const float*)d_in[9],  (const float*)d_in[10],
                                (const float*)d_in[11], (const float*)d_in[12],
                                (const float*)d_in[13], (const float*)d_in[14],
                                out);
    (void)in_sizes; (void)n_in; (void)out_size;
}

// round 14
// speedup vs baseline: 1.0297x; 1.0011x over previous
#include <cuda_runtime.h>
#include <cuda_fp16.h>
#include <cstdint>

// ---------------------------------------------------------------------------
// Problem constants
// ---------------------------------------------------------------------------
static constexpr int Bz   = 8192;   // batch
static constexpr int Hd   = 1024;   // hidden
static constexpr int Ktot = 2048;   // IN + H
static constexpr int Ntot = 4096;   // 4H
static constexpr float EPSV = 1e-5f;

// GEMM tiling: 128x128x64, 3 stages, 4 warps of 64x64, 2 CTAs/SM  (champion)
static constexpr int BM = 128;
static constexpr int BN = 128;
static constexpr int BK = 64;
static constexpr int STAGES = 3;
static constexpr int NTHREADS = 128;

static constexpr int ROW_HALVES = BK + 8;              // 72 halves = 144B padded row
static constexpr int ROW_BYTES  = ROW_HALVES * 2;      // 144
static constexpr int TILE_BYTES = BM * ROW_BYTES;      // 18432 (A); B same
static constexpr int STAGE_BYTES = 2 * TILE_BYTES;     // 36864
static constexpr int SMEM_BYTES  = STAGES * STAGE_BYTES; // 110592 (x2 CTA = 216KB)

static constexpr int NB_M = Bz / BM;    // 64
static constexpr int NB_N = Ntot / BN;  // 32
static constexpr int GM   = 8;          // raster group

// ---------------------------------------------------------------------------
// Static device scratch (allocation-free rule)
// ---------------------------------------------------------------------------
__device__ __half g_A16[(size_t)Bz * Ktot];    // [8192, 2048] fp16  (32 MB)
__device__ __half g_W16[(size_t)Ntot * Ktot];  // [4096, 2048] fp16  (16 MB)
__device__ float  g_G[(size_t)Bz * Ntot];      // [8192, 4096] fp32  (128 MB)

// ---------------------------------------------------------------------------
// PTX helpers (plain sm_80/90 features only)
// ---------------------------------------------------------------------------
__device__ __forceinline__ uint32_t smem_u32(const void* p) {
    uint32_t a;
    asm("{ .reg .u64 t; cvta.to.shared.u64 t, %1; cvt.u32.u64 %0, t; }"
        : "=r"(a) : "l"(p));
    return a;
}

#define CP_ASYNC16(saddr, gptr) \
    asm volatile("cp.async.cg.shared.global [%0], [%1], 16;" \
                 :: "r"(saddr), "l"(gptr) : "memory")
#define CP_COMMIT() asm volatile("cp.async.commit_group;" ::: "memory")
#define CP_WAIT1()  asm volatile("cp.async.wait_group 1;" ::: "memory")

#define LDMATRIX_X4(r0, r1, r2, r3, addr) \
    asm volatile("ldmatrix.sync.aligned.m8n8.x4.shared.b16 {%0,%1,%2,%3}, [%4];" \
                 : "=r"(r0), "=r"(r1), "=r"(r2), "=r"(r3) : "r"(addr))

#define MMA16816(c0, c1, c2, c3, a0, a1, a2, a3, b0, b1) \
    asm volatile("mma.sync.aligned.m16n8k16.row.col.f32.f16.f16.f32 " \
                 "{%0,%1,%2,%3}, {%4,%5,%6,%7}, {%8,%9}, {%0,%1,%2,%3};" \
                 : "+f"(c0), "+f"(c1), "+f"(c2), "+f"(c3) \
                 : "r"(a0), "r"(a1), "r"(a2), "r"(a3), "r"(b0), "r"(b1))

// streaming (evict-first) store for the G intermediate — GEMM never re-reads G,
// so keep it from evicting the reusable A16/W16 panels in L2.
#define STG_CS_V2(ptr, v0, v1) \
    asm volatile("st.global.cs.v2.f32 [%0], {%1, %2};" \
                 :: "l"(ptr), "f"(v0), "f"(v1) : "memory")

// ---------------------------------------------------------------------------
// Kernel 1: pack fp32 inputs/weights -> fp16 A=[x|h], W=[w_i|w_h]
//   32B reads (2x float4) -> 16B STG.128 writes  (R13 champion)
// ---------------------------------------------------------------------------
__global__ void __launch_bounds__(256)
convert_kernel(const float4* __restrict__ x, const float4* __restrict__ h,
               const float4* __restrict__ wi, const float4* __restrict__ wh) {
    const int NA = Bz * 128;     // 8-float items per A half
    const int NW = Ntot * 128;   // 8-float items per W half
    const int total = 2 * NA + 2 * NW;
    int stride = gridDim.x * blockDim.x;
    for (int i = blockIdx.x * blockDim.x + threadIdx.x; i < total; i += stride) {
        const float4* src;
        __half* dst;
        size_t dofs;
        int j;
        if (i < NA) {
            j = i; src = x;
            int m = j >> 7, k8 = j & 127;
            dst = g_A16; dofs = (size_t)m * Ktot + k8 * 8;
        } else if (i < 2 * NA) {
            j = i - NA; src = h;
            int m = j >> 7, k8 = j & 127;
            dst = g_A16; dofs = (size_t)m * Ktot + 1024 + k8 * 8;
        } else if (i < 2 * NA + NW) {
            j = i - 2 * NA; src = wi;
            int n = j >> 7, k8 = j & 127;
            dst = g_W16; dofs = (size_t)n * Ktot + k8 * 8;
        } else {
            j = i - 2 * NA - NW; src = wh;
            int n = j >> 7, k8 = j & 127;
            dst = g_W16; dofs = (size_t)n * Ktot + 1024 + k8 * 8;
        }
        float4 v0 = src[2 * j];
        float4 v1 = src[2 * j + 1];
        __half2 h0 = __floats2half2_rn(v0.x, v0.y);
        __half2 h1 = __floats2half2_rn(v0.z, v0.w);
        __half2 h2 = __floats2half2_rn(v1.x, v1.y);
        __half2 h3 = __floats2half2_rn(v1.z, v1.w);
        uint4 u;
        u.x = *reinterpret_cast<uint32_t*>(&h0);
        u.y = *reinterpret_cast<uint32_t*>(&h1);
        u.z = *reinterpret_cast<uint32_t*>(&h2);
        u.w = *reinterpret_cast<uint32_t*>(&h3);
        *reinterpret_cast<uint4*>(dst + dofs) = u;
    }
}

// ---------------------------------------------------------------------------
// Kernel 2: pipelined mma.sync fp16 GEMM  G[8192,4096] = A16 @ W16^T
//   champion mainloop; epilogue uses streaming stores (st.global.cs)
//   n-tiles in [2048,3072): accumulate only k >= 1024 (dead-chunk bug)
// ---------------------------------------------------------------------------
__global__ void __launch_bounds__(NTHREADS, 2)
gemm_kernel(const __half* __restrict__ A, const __half* __restrict__ W,
            float* __restrict__ G) {
    extern __shared__ __align__(128) char smem[];
    const uint32_t sb = smem_u32(smem);

    const int tid = threadIdx.x;
    const int wid = tid >> 5, lane = tid & 31;

    int pid = blockIdx.x;
    const int per_group = GM * NB_N;
    int bm = (pid / per_group) * GM + (pid % per_group) % GM;
    int bn = (pid % per_group) / GM;
    const int m0 = bm * BM;
    const int n0 = bn * BN;

    const int kstart = (bn >= 16 && bn < 24) ? (1024 / BK) : 0;
    const int nkt    = (Ktot / BK) - kstart;

    int rT[8], cT[8];
    const __half* gA[8]; const __half* gB[8];
    uint32_t sA[8], sB[8];
    #pragma unroll
    for (int j = 0; j < 8; j++) {
        int c = tid + j * NTHREADS;
        rT[j] = c >> 3; cT[j] = c & 7;
        gA[j] = A + (size_t)(m0 + rT[j]) * Ktot + cT[j] * 8;
        gB[j] = W + (size_t)(n0 + rT[j]) * Ktot + cT[j] * 8;
        sA[j] = sb + rT[j] * ROW_BYTES + cT[j] * 16;
        sB[j] = sb + TILE_BYTES + rT[j] * ROW_BYTES + cT[j] * 16;
    }
    const size_t kinc = (size_t)kstart * BK;

    const int wm0 = (wid & 1) * 64;
    const int wn0 = (wid >> 1) * 64;

    const int a_row = wm0 + (lane & 15);
    const int a_kc  = lane >> 4;
    const int b_row = wn0 + ((lane >> 4) << 3) + (lane & 7);
    const int b_kc  = (lane >> 3) & 1;

    float acc[4][8][4];
    #pragma unroll
    for (int i = 0; i < 4; i++)
        #pragma unroll
        for (int j = 0; j < 8; j++)
            #pragma unroll
            for (int c = 0; c < 4; c++) acc[i][j][c] = 0.f;

    #pragma unroll
    for (int s = 0; s < STAGES - 1; s++) {
        size_t ko = kinc + (size_t)s * BK;
        uint32_t so = s * STAGE_BYTES;
        #pragma unroll
        for (int j = 0; j < 8; j++) CP_ASYNC16(sA[j] + so, gA[j] + ko);
        #pragma unroll
        for (int j = 0; j < 8; j++) CP_ASYNC16(sB[j] + so, gB[j] + ko);
        CP_COMMIT();
    }

    int stage = 0, nstage = STAGES - 1;
    for (int kt = 0; kt < nkt; kt++) {
        CP_WAIT1();
        __syncthreads();

        int nx = kt + STAGES - 1;
        if (nx < nkt) {
            size_t ko = kinc + (size_t)nx * BK;
            uint32_t so = nstage * STAGE_BYTES;
            #pragma unroll
            for (int j = 0; j < 8; j++) CP_ASYNC16(sA[j] + so, gA[j] + ko);
            #pragma unroll
            for (int j = 0; j < 8; j++) CP_ASYNC16(sB[j] + so, gB[j] + ko);
        }
        CP_COMMIT();
        if (++nstage == STAGES) nstage = 0;

        const uint32_t stA = sb + stage * STAGE_BYTES;
        const uint32_t stB = stA + TILE_BYTES;
        if (++stage == STAGES) stage = 0;

        #pragma unroll
        for (int ks = 0; ks < 4; ks++) {
            uint32_t a[4][4];
            #pragma unroll
            for (int mt = 0; mt < 4; mt++) {
                uint32_t addr = stA + (a_row + mt * 16) * ROW_BYTES
                              + (ks * 2 + a_kc) * 16;
                LDMATRIX_X4(a[mt][0], a[mt][1], a[mt][2], a[mt][3], addr);
            }
            uint32_t b[8][2];
            #pragma unroll
            for (int p = 0; p < 4; p++) {
                uint32_t addr = stB + (b_row + p * 16) * ROW_BYTES
                              + (ks * 2 + b_kc) * 16;
                uint32_t r0, r1, r2, r3;
                LDMATRIX_X4(r0, r1, r2, r3, addr);
                b[p * 2 + 0][0] = r0; b[p * 2 + 0][1] = r1;
                b[p * 2 + 1][0] = r2; b[p * 2 + 1][1] = r3;
            }
            #pragma unroll
            for (int mt = 0; mt < 4; mt++)
                #pragma unroll
                for (int ng = 0; ng < 8; ng++)
                    MMA16816(acc[mt][ng][0], acc[mt][ng][1],
                             acc[mt][ng][2], acc[mt][ng][3],
                             a[mt][0], a[mt][1], a[mt][2], a[mt][3],
                             b[ng][0], b[ng][1]);
        }
    }

    // ---- epilogue: streaming (evict-first) float2 stores ----
    const int er = lane >> 2;
    const int ec = (lane & 3) * 2;
    #pragma unroll
    for (int mt = 0; mt < 4; mt++) {
        #pragma unroll
        for (int ng = 0; ng < 8; ng++) {
            int row = m0 + wm0 + mt * 16 + er;
            int col = n0 + wn0 + ng * 8 + ec;
            float* p0 = G + (size_t)row * Ntot + col;
            float* p1 = G + (size_t)(row + 8) * Ntot + col;
            STG_CS_V2(p0, acc[mt][ng][0], acc[mt][ng][1]);
            STG_CS_V2(p1, acc[mt][ng][2], acc[mt][ng][3]);
        }
    }
}

// ---------------------------------------------------------------------------
// Kernel 3: per-row LayerNorm-LSTM gating (champion form)
// ---------------------------------------------------------------------------
__device__ __forceinline__ float sigmoidf_(float v) { return 1.f / (1.f + expf(-v)); }

__device__ __forceinline__ void block_reduce(float* v, int cnt, float sh[][6], float* bc) {
    int tid = threadIdx.x, lane = tid & 31, w = tid >> 5;
    #pragma unroll
    for (int c = 0; c < 6; c++) {
        if (c >= cnt) break;
        float xv = v[c];
        #pragma unroll
        for (int o = 16; o; o >>= 1) xv += __shfl_xor_sync(0xffffffffu, xv, o);
        if (lane == 0) sh[w][c] = xv;
    }
    __syncthreads();
    if (tid < cnt) {
        float a = 0.f;
        #pragma unroll
        for (int i = 0; i < 8; i++) a += sh[i][tid];
        bc[tid] = a;
    }
    __syncthreads();
    for (int c = 0; c < cnt; c++) v[c] = bc[c];
}

__global__ void __launch_bounds__(256)
ln_lstm_kernel(const float* __restrict__ G, const float* __restrict__ c_prev,
               const float* __restrict__ li_g, const float* __restrict__ li_b,
               const float* __restrict__ lh_g, const float* __restrict__ lh_b,
               const float* __restrict__ lg_g, const float* __restrict__ lg_b,
               const float* __restrict__ lo_g, const float* __restrict__ lo_b,
               const float* __restrict__ lc_g, const float* __restrict__ lc_b,
               float* __restrict__ out) {
    __shared__ float sh[8][6];
    __shared__ float bc[6];
    int b = blockIdx.x, tid = threadIdx.x;
    const float* g = G + (size_t)b * Ntot;
    const float inv = 1.f / 1024.f;

    float a0[4], a1[4], a2[4], a3[4], cp[4];
    float s[6] = {0.f, 0.f, 0.f, 0.f, 0.f, 0.f};
    #pragma unroll
    for (int j = 0; j < 4; j++) {
        int n = tid + j * 256;
        a0[j] = g[n];
        a1[j] = g[1024 + n];
        a2[j] = g[2048 + n];     // = h_g preactivation (w_h-only column block)
        a3[j] = g[3072 + n];
        cp[j] = c_prev[(size_t)b * Hd + n];
        s[0] += a0[j]; s[1] += a0[j] * a0[j];
        s[2] += a1[j]; s[3] += a1[j] * a1[j];
        s[4] += a3[j]; s[5] += a3[j] * a3[j];
    }
    block_reduce(s, 6, sh, bc);
    float mu0 = s[0] * inv, r0 = rsqrtf(s[1] * inv - mu0 * mu0 + EPSV);
    float mu1 = s[2] * inv, r1 = rsqrtf(s[3] * inv - mu1 * mu1 + EPSV);
    float mu3 = s[4] * inv, r3 = rsqrtf(s[5] * inv - mu3 * mu3 + EPSV);

    float ig[4], fg[4], og[4], tt[4];
    float t[6] = {0.f, 0.f, 0.f, 0.f, 0.f, 0.f};
    #pragma unroll
    for (int j = 0; j < 4; j++) {
        int n = tid + j * 256;
        ig[j] = sigmoidf_((a0[j] - mu0) * r0 * li_g[n] + li_b[n]);
        fg[j] = sigmoidf_((a1[j] - mu1) * r1 * lh_g[n] + lh_b[n]);
        og[j] = sigmoidf_((a3[j] - mu3) * r3 * lo_g[n] + lo_b[n]);
        tt[j] = ig[j] + a2[j];       // source bug: sigmoided i_g + h_g
        t[0] += tt[j]; t[1] += tt[j] * tt[j];
    }
    block_reduce(t, 2, sh, bc);
    float mut = t[0] * inv, rt = rsqrtf(t[1] * inv - mut * mut + EPSV);

    float cl[4];
    float u[6] = {0.f, 0.f, 0.f, 0.f, 0.f, 0.f};
    #pragma unroll
    for (int j = 0; j < 4; j++) {
        int n = tid + j * 256;
        float gg = tanhf((tt[j] - mut) * rt * lg_g[n] + lg_b[n]);
        cl[j] = fg[j] * cp[j] + ig[j] * gg;
        u[0] += cl[j]; u[1] += cl[j] * cl[j];
    }
    block_reduce(u, 2, sh, bc);
    float muc = u[0] * inv, rc = rsqrtf(u[1] * inv - muc * muc + EPSV);

    #pragma unroll
    for (int j = 0; j < 4; j++) {
        int n = tid + j * 256;
        float cn = (cl[j] - muc) * rc * lc_g[n] + lc_b[n];
        out[(size_t)Bz * Hd + (size_t)b * Hd + n] = cn;             // c_new
        out[(size_t)b * Hd + n] = og[j] * tanhf(cn);                // h_new
    }
}

// ---------------------------------------------------------------------------
// Host
// ---------------------------------------------------------------------------
extern "C" void kernel_launch(void* const* d_in, const int* in_sizes, int n_in,
                              void* d_out, int out_size) {
    const float* x  = (const float*)d_in[0];
    const float* h  = (const float*)d_in[1];
    const float* c  = (const float*)d_in[2];
    const float* wi = (const float*)d_in[3];
    const float* wh = (const float*)d_in[4];
    float* out = (float*)d_out;

    void *pA = nullptr, *pW = nullptr, *pG = nullptr;
    cudaGetSymbolAddress(&pA, g_A16);
    cudaGetSymbolAddress(&pW, g_W16);
    cudaGetSymbolAddress(&pG, g_G);

    cudaFuncSetAttribute(gemm_kernel, cudaFuncAttributeMaxDynamicSharedMemorySize,
                         SMEM_BYTES);

    convert_kernel<<<1184, 256>>>((const float4*)x, (const float4*)h,
                                  (const float4*)wi, (const float4*)wh);

    gemm_kernel<<<NB_M * NB_N, NTHREADS, SMEM_BYTES>>>((const __half*)pA,
                                                       (const __half*)pW,
                                                       (float*)pG);

    ln_lstm_kernel<<<Bz, 256>>>((const float*)pG, c,
                                (const float*)d_in[5],  (const float*)d_in[6],
                                (const float*)d_in[7],  (const float*)d_in[8],
                                (const float*)d_in[9],  (const float*)d_in[10],
                                (const float*)d_in[11], (const float*)d_in[12],
                                (const float*)d_in[13], (const float*)d_in[14],
                                out);
    (void)in_sizes; (void)n_in; (void)out_size;
}